// round 4
// baseline (speedup 1.0000x reference)
#include <cuda_runtime.h>
#include <math.h>
#include <stdint.h>

#define B_TOTAL 131072
#define DIM     128
#define HID     256
#define NB      8
#define NL      4
#define KSEL    2
#define FIN     32
#define ROWS    128      // rows per CTA tile
#define LDH     132      // padded stride (floats)

typedef unsigned long long u64;

__device__ int   g_sel[NL * KSEL];
__device__ float g_gfac[NL * KSEL][DIM];
// Pre-packed weights: 8 slots x 32 chunks x 1024 u64 (8KB/chunk) = 2 MB,
// laid out in exact consumption order (slot-major, then seq 0..31).
__device__ __align__(256) u64 g_wpack[8 * 32 * 1024];

__device__ __forceinline__ float sigm(float x) { return 1.0f / (1.0f + expf(-x)); }
__device__ __forceinline__ float gelu_exact(float x) {
    return 0.5f * x * (1.0f + erff(x * 0.70710678118654752440f));
}
__device__ __forceinline__ uint32_t tf32cvt(float x) {
    uint32_t r; asm("cvt.rna.tf32.f32 %0, %1;" : "=r"(r) : "f"(x)); return r;
}
__device__ __forceinline__ void mma_tf32(float c[4], const uint32_t a[4],
                                         uint32_t b0, uint32_t b1) {
    asm("mma.sync.aligned.m16n8k8.row.col.f32.tf32.tf32.f32 "
        "{%0,%1,%2,%3},{%4,%5,%6,%7},{%8,%9},{%0,%1,%2,%3};"
        : "+f"(c[0]), "+f"(c[1]), "+f"(c[2]), "+f"(c[3])
        : "r"(a[0]), "r"(a[1]), "r"(a[2]), "r"(a[3]), "r"(b0), "r"(b1));
}
__device__ __forceinline__ void cp16(uint32_t daddr, const void* src) {
    asm volatile("cp.async.cg.shared.global [%0], [%1], 16;" :: "r"(daddr), "l"(src));
}

// ---------------------------------------------------------------------------
// Pilot: sample-0 trajectory -> routing + gate factors (proven in R2/R3)
// ---------------------------------------------------------------------------
__global__ void pilot_kernel(const float* __restrict__ x, const float* __restrict__ pw,
                             const float* __restrict__ pb, const float* __restrict__ pos,
                             const float* __restrict__ sel_w, const float* __restrict__ sel_b,
                             const float* __restrict__ ln_s, const float* __restrict__ ln_b,
                             const float* __restrict__ w1, const float* __restrict__ b1,
                             const float* __restrict__ w2, const float* __restrict__ b2,
                             const float* __restrict__ gate, const float* __restrict__ tf) {
    __shared__ float h0[DIM], hn[DIM], tbuf[HID], fbuf[DIM];
    __shared__ float redA[64], redB[64];
    __shared__ float sc[NB];
    __shared__ int   seli[KSEL];
    __shared__ float s_mu, s_rstd;
    int tid = threadIdx.x;   // 256

    if (tid < DIM) {
        float acc = pb[tid] + pos[tid];
#pragma unroll
        for (int k = 0; k < FIN; k++) acc += x[k] * pw[k * DIM + tid];
        h0[tid] = acc;
    }
    __syncthreads();

    for (int l = 0; l < NL; l++) {
        if (tid < NB) {
            float s = sel_b[l * NB + tid];
            for (int d = 0; d < DIM; d++) s += h0[d] * sel_w[(l * DIM + d) * NB + tid];
            sc[tid] = sigm(s) * 0.6f + 0.2f;
        }
        __syncthreads();
        if (tid == 0) {
            int i0 = 0; float v0 = -1e30f;
            for (int j = 0; j < NB; j++) if (sc[j] > v0) { v0 = sc[j]; i0 = j; }
            int i1 = -1; float v1 = -1e30f;
            for (int j = 0; j < NB; j++) { if (j == i0) continue; if (sc[j] > v1) { v1 = sc[j]; i1 = j; } }
            seli[0] = i0; seli[1] = i1;
            g_sel[l * KSEL + 0] = i0; g_sel[l * KSEL + 1] = i1;
        }
        __syncthreads();

        for (int k = 0; k < KSEL; k++) {
            int i = seli[k];
            size_t bo = (size_t)(l * NB + i);
            if (tid < DIM) {
                float fv = 1.0f + sigm(gate[bo * DIM + tid]) * tf[tid];
                fbuf[tid] = fv;
                g_gfac[l * KSEL + k][tid] = fv;
            }
            if (tid < 64) {
                float a = h0[tid], b = h0[tid + 64];
                redA[tid] = a + b; redB[tid] = a * a + b * b;
            }
            __syncthreads();
            if (tid == 0) {
                float s = 0.f, q = 0.f;
                for (int j = 0; j < 64; j++) { s += redA[j]; q += redB[j]; }
                float mu = s * (1.0f / DIM);
                s_mu = mu;
                s_rstd = rsqrtf(q * (1.0f / DIM) - mu * mu + 1e-5f);
            }
            __syncthreads();
            if (tid < DIM)
                hn[tid] = (h0[tid] - s_mu) * s_rstd * ln_s[bo * DIM + tid] + ln_b[bo * DIM + tid];
            __syncthreads();
            {
                float acc = b1[bo * HID + tid];
                const float* W1 = w1 + bo * DIM * HID;
                for (int d = 0; d < DIM; d++) acc += hn[d] * W1[(size_t)d * HID + tid];
                tbuf[tid] = gelu_exact(acc);
            }
            __syncthreads();
            if (tid < DIM) {
                float acc = b2[bo * DIM + tid];
                const float* W2 = w2 + bo * HID * DIM;
                for (int j = 0; j < HID; j++) acc += tbuf[j] * W2[(size_t)j * DIM + tid];
                h0[tid] += 0.5f * acc * fbuf[tid];
            }
            __syncthreads();
        }
    }
}

// ---------------------------------------------------------------------------
// Repack: selected experts' W1/W2 -> fragment-paired tf32 u64 chunks.
// chunk seq per slot: s4 = seq/8 (0:G1 half0, 1:G2 half0, 2:G1 half1, 3:G2 half1),
// kc = seq%8 (16 k-rows per chunk). Entry e in [0,1024):
//   lane=e%32, n8=(e/32)%16, ks=e/512, kq=lane%4, nq=lane/4
//   lo = W[kbase+ks*8+kq][nbase+n8*8+nq], hi = W[kbase+ks*8+kq+4][same n]
// ---------------------------------------------------------------------------
__global__ void repack_kernel(const float* __restrict__ w1g, const float* __restrict__ w2g) {
    int chunk = blockIdx.x;            // 0..255
    int slot = chunk >> 5, seq = chunk & 31;
    int s4 = seq >> 3, kc = seq & 7;
    int half = s4 >> 1;
    bool isG1 = !(s4 & 1);
    int layer = slot >> 1;
    int blk = g_sel[slot];
    size_t bo = (size_t)(layer * NB + blk);
    const float* W; int ldn, kbase, nbase;
    if (isG1) { W = w1g + bo * DIM * HID; ldn = HID; kbase = kc * 16;              nbase = half * 128; }
    else      { W = w2g + bo * HID * DIM; ldn = DIM; kbase = half * 128 + kc * 16; nbase = 0; }
    u64* dst = g_wpack + (size_t)chunk * 1024;
    for (int e = threadIdx.x; e < 1024; e += 256) {
        int lane = e & 31, n8 = (e >> 5) & 15, ks = e >> 9;
        int kq = lane & 3, nq = lane >> 2;
        int k = kbase + ks * 8 + kq, n = nbase + n8 * 8 + nq;
        uint32_t lo = tf32cvt(W[(size_t)k * ldn + n]);
        uint32_t hi = tf32cvt(W[(size_t)(k + 4) * ldn + n]);
        dst[e] = (u64)lo | ((u64)hi << 32);
    }
}

// ---------------------------------------------------------------------------
// Fused: proj -> 8 expert blocks (tf32 mma, cp.async streamed weights) -> head
// ---------------------------------------------------------------------------
__global__ void __launch_bounds__(256, 1)
fused_kernel(const float* __restrict__ xg, const float* __restrict__ pw,
             const float* __restrict__ pb, const float* __restrict__ pos,
             const float* __restrict__ b1g, const float* __restrict__ b2g,
             const float* __restrict__ ln_s, const float* __restrict__ ln_b,
             const float* __restrict__ cls_w, const float* __restrict__ cls_b,
             float* __restrict__ out) {
    extern __shared__ float sm[];
    float*    s_h  = sm;                                   // [ROWS][LDH] fp32
    uint32_t* s_hn = (uint32_t*)(sm + ROWS * LDH);         // [ROWS][LDH] tf32
    uint32_t* s_t  = (uint32_t*)(sm + 2 * ROWS * LDH);     // [ROWS][LDH] tf32
    u64*      s_wb = (u64*)(sm + 3 * ROWS * LDH);          // 2 x 1024 u64 (16 KB)

    int tid = threadIdx.x, lane = tid & 31, wid = tid >> 5;
    int wm = wid >> 1, wn = wid & 1;          // 4 x 2 warp tiling
    int g = lane >> 2, tg = lane & 3;
    int mrow = wm * 32;
    size_t row0 = (size_t)blockIdx.x * ROWS;

    uint32_t wb_addr[2];
    wb_addr[0] = (uint32_t)__cvta_generic_to_shared(s_wb);
    wb_addr[1] = wb_addr[0] + 8192;

    // issue chunk 0 (arrives during projection)
    {
        uint32_t d = wb_addr[0] + tid * 32;
        const char* s = (const char*)g_wpack + tid * 32;
        cp16(d, s); cp16(d + 16, s + 16);
        asm volatile("cp.async.commit_group;");
    }

    // ================= input projection =================
    {
        float* s_x  = (float*)s_hn;   // [128][36] scratch
        float* s_pw = (float*)s_t;    // [32][LDH] scratch
        for (int i = tid; i < 1024; i += 256) {
            int r = i >> 5, c4 = i & 31;
            float4 v = *(const float4*)(pw + r * DIM + c4 * 4);
            *(float4*)&s_pw[r * LDH + c4 * 4] = v;
        }
        for (int i = tid; i < 1024; i += 256) {
            int r = i >> 3, c4 = i & 7;
            float4 v = *(const float4*)(xg + (row0 + r) * FIN + c4 * 4);
            *(float4*)&s_x[r * 36 + c4 * 4] = v;
        }
        __syncthreads();
        int pr = tid >> 1, ph = tid & 1;
        float acc[16][4];
#pragma unroll
        for (int c4 = 0; c4 < 16; c4++) {
            int col = ph * 64 + c4 * 4;
            float4 a = *(const float4*)(pb + col);
            float4 po = *(const float4*)(pos + col);
            acc[c4][0] = a.x + po.x; acc[c4][1] = a.y + po.y;
            acc[c4][2] = a.z + po.z; acc[c4][3] = a.w + po.w;
        }
#pragma unroll 8
        for (int k = 0; k < FIN; k++) {
            float a = s_x[pr * 36 + k];
#pragma unroll
            for (int c4 = 0; c4 < 16; c4++) {
                int col = ph * 64 + c4 * 4;
                float4 w = *(const float4*)&s_pw[k * LDH + col];
                acc[c4][0] += a * w.x; acc[c4][1] += a * w.y;
                acc[c4][2] += a * w.z; acc[c4][3] += a * w.w;
            }
        }
        __syncthreads();   // done reading scratch before h write? (h separate) — keep for s_x/s_pw reuse safety
#pragma unroll
        for (int c4 = 0; c4 < 16; c4++) {
            int col = ph * 64 + c4 * 4;
            float4 o; o.x = acc[c4][0]; o.y = acc[c4][1]; o.z = acc[c4][2]; o.w = acc[c4][3];
            *(float4*)&s_h[pr * LDH + col] = o;
        }
        __syncthreads();
    }

    // ============================ 8 expert slots ============================
    for (int slot = 0; slot < NL * KSEL; slot++) {
        const float* B1 = b1g;  // offsets resolved via packed biases below
        // biases/LN params need the selected block:
        int blk = g_sel[slot];
        size_t bo = (size_t)((slot >> 1) * NB + blk);
        const float* LS = ln_s + bo * DIM;
        const float* LB = ln_b + bo * DIM;
        const float* B1p = b1g + bo * HID;
        const float* B2p = b2g + bo * DIM;

        // ---- LayerNorm -> s_hn (tf32) ----
        {
            float4 ls4 = *(const float4*)(LS + lane * 4);
            float4 lb4 = *(const float4*)(LB + lane * 4);
#pragma unroll 4
            for (int rr = 0; rr < 16; rr++) {
                int r = wid * 16 + rr;
                float4 v = *(const float4*)&s_h[r * LDH + lane * 4];
                float s = v.x + v.y + v.z + v.w;
                float q = v.x * v.x + v.y * v.y + v.z * v.z + v.w * v.w;
#pragma unroll
                for (int o = 16; o > 0; o >>= 1) {
                    s += __shfl_xor_sync(0xffffffffu, s, o);
                    q += __shfl_xor_sync(0xffffffffu, q, o);
                }
                float mu = s * (1.0f / DIM);
                float rstd = rsqrtf(q * (1.0f / DIM) - mu * mu + 1e-5f);
                uint4 o4;
                o4.x = tf32cvt((v.x - mu) * rstd * ls4.x + lb4.x);
                o4.y = tf32cvt((v.y - mu) * rstd * ls4.y + lb4.y);
                o4.z = tf32cvt((v.z - mu) * rstd * ls4.z + lb4.z);
                o4.w = tf32cvt((v.w - mu) * rstd * ls4.w + lb4.w);
                *(uint4*)&s_hn[r * LDH + lane * 4] = o4;
            }
        }
        // (no standalone sync needed: first chunk's __syncthreads below covers it)

        float zacc[2][8][4];
#pragma unroll
        for (int mi = 0; mi < 2; mi++)
#pragma unroll
            for (int j = 0; j < 8; j++)
#pragma unroll
                for (int e = 0; e < 4; e++) zacc[mi][j][e] = 0.0f;

        float c1[2][8][4];

        for (int s4 = 0; s4 < 4; s4++) {
            bool isG1 = !(s4 & 1);
            int half = s4 >> 1;
            if (isG1) {
#pragma unroll
                for (int mi = 0; mi < 2; mi++)
#pragma unroll
                    for (int j = 0; j < 8; j++)
#pragma unroll
                        for (int e = 0; e < 4; e++) c1[mi][j][e] = 0.0f;
            }
            const uint32_t* Asrc = isG1 ? s_hn : s_t;

            for (int kc = 0; kc < 8; kc++) {
                int seq = s4 * 8 + kc;
                asm volatile("cp.async.wait_group 0;" ::: "memory");
                __syncthreads();
                int nxt = slot * 32 + seq + 1;
                if (nxt < 256) {
                    uint32_t d = wb_addr[(seq + 1) & 1] + tid * 32;
                    const char* sp = (const char*)(g_wpack + (size_t)nxt * 1024) + tid * 32;
                    cp16(d, sp); cp16(d + 16, sp + 16);
                }
                asm volatile("cp.async.commit_group;");

                const u64* buf = (seq & 1) ? (s_wb + 1024) : s_wb;
                float (*acc)[8][4] = isG1 ? c1 : zacc;
#pragma unroll
                for (int ks = 0; ks < 2; ks++) {
                    int k0 = kc * 16 + ks * 8;
                    uint32_t a[2][4];
#pragma unroll
                    for (int mi = 0; mi < 2; mi++) {
                        int r = mrow + mi * 16 + g;
                        a[mi][0] = Asrc[r * LDH + k0 + tg];
                        a[mi][1] = Asrc[(r + 8) * LDH + k0 + tg];
                        a[mi][2] = Asrc[r * LDH + k0 + tg + 4];
                        a[mi][3] = Asrc[(r + 8) * LDH + k0 + tg + 4];
                    }
                    const u64* bp = buf + (ks * 16 + wn * 8) * 32 + lane;
#pragma unroll
                    for (int j = 0; j < 8; j++) {
                        u64 b = bp[j * 32];
                        uint32_t b0 = (uint32_t)b, b1 = (uint32_t)(b >> 32);
                        mma_tf32(acc[0][j], a[0], b0, b1);
                        mma_tf32(acc[1][j], a[1], b0, b1);
                    }
                }
            }

            if (isG1) {
                // +b1, GELU -> s_t (tf32). Next chunk's syncthreads orders it
                // before any warp reads s_t in the G2 phase.
                __syncthreads();   // all warps done reading s_t? (s_t last read prev slot G2; also ensures hn reads done before... s_t distinct) — ensure no warp still in prev phase reading s_t cols being overwritten
#pragma unroll
                for (int mi = 0; mi < 2; mi++)
#pragma unroll
                    for (int j = 0; j < 8; j++) {
                        int col = wn * 64 + j * 8 + tg * 2;
                        float2 bb = *(const float2*)(B1p + half * 128 + col);
                        int r = mrow + mi * 16 + g;
                        float t0 = gelu_exact(c1[mi][j][0] + bb.x);
                        float t1 = gelu_exact(c1[mi][j][1] + bb.y);
                        u64 p = (u64)tf32cvt(t0) | ((u64)tf32cvt(t1) << 32);
                        *(u64*)&s_t[r * LDH + col] = p;
                        t0 = gelu_exact(c1[mi][j][2] + bb.x);
                        t1 = gelu_exact(c1[mi][j][3] + bb.y);
                        p = (u64)tf32cvt(t0) | ((u64)tf32cvt(t1) << 32);
                        *(u64*)&s_t[(r + 8) * LDH + col] = p;
                    }
            }
        }

        // ---- residual epilogue: h += 0.5 * (z + b2) * gfac ----
        __syncthreads();   // all warps finished reading s_h-dependent data (LN long done) & s_t reads done
#pragma unroll
        for (int mi = 0; mi < 2; mi++)
#pragma unroll
            for (int j = 0; j < 8; j++) {
                int col = wn * 64 + j * 8 + tg * 2;
                float2 b2v = *(const float2*)(B2p + col);
                float2 fv  = *(const float2*)(&g_gfac[slot][col]);
                int r = mrow + mi * 16 + g;
                float* hp = &s_h[r * LDH + col];
                hp[0] += 0.5f * (zacc[mi][j][0] + b2v.x) * fv.x;
                hp[1] += 0.5f * (zacc[mi][j][1] + b2v.y) * fv.y;
                float* hp2 = &s_h[(r + 8) * LDH + col];
                hp2[0] += 0.5f * (zacc[mi][j][2] + b2v.x) * fv.x;
                hp2[1] += 0.5f * (zacc[mi][j][3] + b2v.y) * fv.y;
            }
        __syncthreads();
    }

    // ============================ classifier + emit ============================
    {
        float2 cw[4];
#pragma unroll
        for (int ci = 0; ci < 4; ci++)
            cw[ci] = *(const float2*)(cls_w + (lane * 4 + ci) * 2);
        float cb0 = cls_b[0], cb1 = cls_b[1];
#pragma unroll 4
        for (int rr = 0; rr < 16; rr++) {
            int r = wid * 16 + rr;
            float4 v = *(const float4*)&s_h[r * LDH + lane * 4];
            float a0 = v.x * cw[0].x + v.y * cw[1].x + v.z * cw[2].x + v.w * cw[3].x;
            float a1 = v.x * cw[0].y + v.y * cw[1].y + v.z * cw[2].y + v.w * cw[3].y;
#pragma unroll
            for (int o = 16; o > 0; o >>= 1) {
                a0 += __shfl_xor_sync(0xffffffffu, a0, o);
                a1 += __shfl_xor_sync(0xffffffffu, a1, o);
            }
            if (lane == 0) {
                size_t row = row0 + r;
                out[row * 2]     = a0 + cb0;
                out[row * 2 + 1] = a1 + cb1;
            }
        }
        for (int i = tid; i < ROWS * 32; i += 256) {
            int r = i >> 5, c = (i & 31) * 4;
            *(float4*)&out[(size_t)B_TOTAL * 2 + (row0 + r) * DIM + c] =
                *(const float4*)&s_h[r * LDH + c];
        }
    }
}

// ---------------------------------------------------------------------------
extern "C" void kernel_launch(void* const* d_in, const int* in_sizes, int n_in,
                              void* d_out, int out_size) {
    const float* x      = (const float*)d_in[0];
    const float* proj_w = (const float*)d_in[1];
    const float* proj_b = (const float*)d_in[2];
    const float* pos    = (const float*)d_in[3];
    const float* sel_w  = (const float*)d_in[4];
    const float* sel_b  = (const float*)d_in[5];
    const float* ln_s   = (const float*)d_in[6];
    const float* ln_b   = (const float*)d_in[7];
    const float* w1     = (const float*)d_in[8];
    const float* b1     = (const float*)d_in[9];
    const float* w2     = (const float*)d_in[10];
    const float* b2     = (const float*)d_in[11];
    const float* gate   = (const float*)d_in[12];
    const float* cls_w  = (const float*)d_in[13];
    const float* cls_b  = (const float*)d_in[14];
    const float* tf     = (const float*)d_in[15];
    float* out = (float*)d_out;

    const int smem_bytes = (3 * ROWS * LDH) * sizeof(float) + 2 * 8192;  // 219136 B
    cudaFuncSetAttribute(fused_kernel, cudaFuncAttributeMaxDynamicSharedMemorySize, smem_bytes);

    pilot_kernel<<<1, 256>>>(x, proj_w, proj_b, pos, sel_w, sel_b, ln_s, ln_b,
                             w1, b1, w2, b2, gate, tf);
    repack_kernel<<<256, 256>>>(w1, w2);
    fused_kernel<<<B_TOTAL / ROWS, 256, smem_bytes>>>(
        x, proj_w, proj_b, pos, b1, b2, ln_s, ln_b, cls_w, cls_b, out);
}

// round 6
// speedup vs baseline: 2.7759x; 2.7759x over previous
#include <cuda_runtime.h>
#include <cuda_fp16.h>
#include <math.h>
#include <stdint.h>

#define B_TOTAL 131072
#define DIM     128
#define HID     256
#define NB      8
#define NL      4
#define KSEL    2
#define FIN     32
#define ROWS    128
#define LDH     132          // s_h float stride
#define SHN_LD  136          // fp16 tile stride (halves)
#define THREADS 512

typedef unsigned long long u64;

__device__ int   g_sel[NL * KSEL];
__device__ float g_gfac[NL * KSEL][DIM];
// 32 chunks x 32KB = 1MB fragment tables: u64[ks(8)][jj(16)][lane(32)] per chunk
__device__ __align__(256) uint4 g_wpack[65536];

__device__ __forceinline__ float sigm(float x) { return 1.0f / (1.0f + expf(-x)); }
__device__ __forceinline__ float gelu_exact(float x) {
    return 0.5f * x * (1.0f + erff(x * 0.70710678118654752440f));
}
__device__ __forceinline__ uint32_t pkh2(float x, float y) {
    return (uint32_t)__half_as_ushort(__float2half_rn(x))
         | ((uint32_t)__half_as_ushort(__float2half_rn(y)) << 16);
}
__device__ __forceinline__ void cp16(uint32_t d, const void* s) {
    asm volatile("cp.async.cg.shared.global [%0], [%1], 16;" :: "r"(d), "l"(s));
}
__device__ __forceinline__ void mma_fp16(float c[4], uint32_t a0, uint32_t a1,
                                         uint32_t a2, uint32_t a3,
                                         uint32_t b0, uint32_t b1) {
    asm volatile("mma.sync.aligned.m16n8k16.row.col.f32.f16.f16.f32 "
        "{%0,%1,%2,%3},{%4,%5,%6,%7},{%8,%9},{%0,%1,%2,%3};"
        : "+f"(c[0]), "+f"(c[1]), "+f"(c[2]), "+f"(c[3])
        : "r"(a0), "r"(a1), "r"(a2), "r"(a3), "r"(b0), "r"(b1));
}

// ---------------------------------------------------------------------------
// Pilot: sample-0 trajectory -> routing + gate factors
// ---------------------------------------------------------------------------
__global__ void pilot_kernel(const float* __restrict__ x, const float* __restrict__ pw,
                             const float* __restrict__ pb, const float* __restrict__ pos,
                             const float* __restrict__ sel_w, const float* __restrict__ sel_b,
                             const float* __restrict__ ln_s, const float* __restrict__ ln_b,
                             const float* __restrict__ w1, const float* __restrict__ b1,
                             const float* __restrict__ w2, const float* __restrict__ b2,
                             const float* __restrict__ gate, const float* __restrict__ tf) {
    __shared__ float h0[DIM], hn[DIM], tbuf[HID], fbuf[DIM];
    __shared__ float redA[64], redB[64];
    __shared__ float sc[NB];
    __shared__ int   seli[KSEL];
    __shared__ float s_mu, s_rstd;
    int tid = threadIdx.x, lane = tid & 31, wid = tid >> 5;

    if (tid < DIM) {
        float acc = pb[tid] + pos[tid];
#pragma unroll
        for (int k = 0; k < FIN; k++) acc += x[k] * pw[k * DIM + tid];
        h0[tid] = acc;
    }
    __syncthreads();

    for (int l = 0; l < NL; l++) {
        {   // selector: warp `wid` computes block `wid`
            float partial = 0.f;
#pragma unroll
            for (int t = 0; t < 4; t++) {
                int d = t * 32 + lane;
                partial += h0[d] * sel_w[(l * DIM + d) * NB + wid];
            }
#pragma unroll
            for (int o = 16; o > 0; o >>= 1) partial += __shfl_xor_sync(0xffffffffu, partial, o);
            if (lane == 0) sc[wid] = sigm(partial + sel_b[l * NB + wid]) * 0.6f + 0.2f;
        }
        __syncthreads();
        if (tid == 0) {
            int i0 = 0; float v0 = -1e30f;
            for (int j = 0; j < NB; j++) if (sc[j] > v0) { v0 = sc[j]; i0 = j; }
            int i1 = -1; float v1 = -1e30f;
            for (int j = 0; j < NB; j++) { if (j == i0) continue; if (sc[j] > v1) { v1 = sc[j]; i1 = j; } }
            seli[0] = i0; seli[1] = i1;
            g_sel[l * KSEL + 0] = i0; g_sel[l * KSEL + 1] = i1;
        }
        __syncthreads();

        for (int k = 0; k < KSEL; k++) {
            int i = seli[k];
            size_t bo = (size_t)(l * NB + i);
            if (tid < DIM) {
                float fv = 1.0f + sigm(gate[bo * DIM + tid]) * tf[tid];
                fbuf[tid] = fv;
                g_gfac[l * KSEL + k][tid] = fv;
            }
            if (tid < 64) {
                float a = h0[tid], b = h0[tid + 64];
                redA[tid] = a + b; redB[tid] = a * a + b * b;
            }
            __syncthreads();
            if (tid == 0) {
                float s = 0.f, q = 0.f;
                for (int j = 0; j < 64; j++) { s += redA[j]; q += redB[j]; }
                float mu = s * (1.0f / DIM);
                s_mu = mu;
                s_rstd = rsqrtf(q * (1.0f / DIM) - mu * mu + 1e-5f);
            }
            __syncthreads();
            if (tid < DIM)
                hn[tid] = (h0[tid] - s_mu) * s_rstd * ln_s[bo * DIM + tid] + ln_b[bo * DIM + tid];
            __syncthreads();
            {
                float acc = b1[bo * HID + tid];
                const float* W1 = w1 + bo * DIM * HID;
#pragma unroll
                for (int d = 0; d < DIM; d++) acc += hn[d] * __ldg(&W1[(size_t)d * HID + tid]);
                tbuf[tid] = gelu_exact(acc);
            }
            __syncthreads();
            if (tid < DIM) {
                float acc = b2[bo * DIM + tid];
                const float* W2 = w2 + bo * HID * DIM;
#pragma unroll 16
                for (int j = 0; j < HID; j++) acc += tbuf[j] * __ldg(&W2[(size_t)j * DIM + tid]);
                h0[tid] += 0.5f * acc * fbuf[tid];
            }
            __syncthreads();
        }
    }
}

// ---------------------------------------------------------------------------
// Repack: selected experts -> per-lane fp16 fragment tables.
// chunk q = slot*4 + phase; phase: 0 G1h0, 1 G2h0, 2 G1h1, 3 G2h1
// entry e = (ks*16 + jj)*32 + lane:
//   b0 = {W[kb+2tg][n], W[kb+2tg+1][n]}  b1 = {W[kb+2tg+8][n], W[kb+2tg+9][n]}
//   G1: n = half*128 + jj*8 + g, kb = ks*16      (W1, ld=HID)
//   G2: n = jj*8 + g,           kb = half*128+ks*16 (W2, ld=DIM)
// ---------------------------------------------------------------------------
__global__ void repack_kernel(const float* __restrict__ w1g, const float* __restrict__ w2g) {
    int q = blockIdx.x;                 // 0..31
    int slot = q >> 2, phase = q & 3;
    int half = phase >> 1;
    bool isG2 = phase & 1;
    int blk = g_sel[slot];
    size_t bo = (size_t)((slot >> 1) * NB + blk);
    const float* W = isG2 ? (w2g + bo * HID * DIM) : (w1g + bo * DIM * HID);
    int ld = isG2 ? DIM : HID;
    u64* dst = (u64*)g_wpack + (size_t)q * 4096;
    for (int e = threadIdx.x; e < 4096; e += 256) {
        int lane = e & 31, jj = (e >> 5) & 15, ks = e >> 9;
        int g = lane >> 2, tg = lane & 3;
        int n, kb;
        if (!isG2) { n = half * 128 + jj * 8 + g; kb = ks * 16; }
        else       { n = jj * 8 + g;              kb = half * 128 + ks * 16; }
        uint32_t lo = pkh2(W[(size_t)(kb + 2 * tg) * ld + n],
                           W[(size_t)(kb + 2 * tg + 1) * ld + n]);
        uint32_t hi = pkh2(W[(size_t)(kb + 2 * tg + 8) * ld + n],
                           W[(size_t)(kb + 2 * tg + 9) * ld + n]);
        dst[e] = (u64)lo | ((u64)hi << 32);
    }
}

// ---------------------------------------------------------------------------
// SMEM byte offsets
// ---------------------------------------------------------------------------
#define OFF_H    0                    // 128*132*4 = 67584
#define OFF_HN   67584                // 128*136*2 = 34816
#define OFF_T    102400               // 128*136*2 = 34816
#define OFF_WB   137216               // 2 x 32768 = 65536
#define OFF_B1   202752               // 1024
#define OFF_B2   203776               // 512
#define OFF_GF   204288               // 512
#define SMEM_TOT 204800

// ---------------------------------------------------------------------------
// Fused: proj -> 8 expert blocks (fp16 mma) -> classifier
// ---------------------------------------------------------------------------
__global__ void __launch_bounds__(THREADS, 1)
fused_kernel(const float* __restrict__ xg, const float* __restrict__ pw,
             const float* __restrict__ pb, const float* __restrict__ pos,
             const float* __restrict__ b1g, const float* __restrict__ b2g,
             const float* __restrict__ ln_s, const float* __restrict__ ln_b,
             const float* __restrict__ cls_w, const float* __restrict__ cls_b,
             float* __restrict__ out) {
    extern __shared__ char smem[];
    float*  s_h  = (float*)(smem + OFF_H);
    __half* s_hn = (__half*)(smem + OFF_HN);
    __half* s_t  = (__half*)(smem + OFF_T);
    float*  s_b1 = (float*)(smem + OFF_B1);
    float*  s_b2 = (float*)(smem + OFF_B2);
    float*  s_gf = (float*)(smem + OFF_GF);

    int tid = threadIdx.x, lane = tid & 31, wid = tid >> 5;
    int wm = wid >> 1, wn = wid & 1;          // 8 x 2 warp grid
    int g = lane >> 2, tg = lane & 3;
    int mrow = wm * 16;
    size_t row0 = (size_t)blockIdx.x * ROWS;
    uint32_t wb = (uint32_t)__cvta_generic_to_shared(smem + OFF_WB);

    // prefetch chunk 0 (overlaps projection)
    {
        uint32_t d = wb + tid * 16;
        const char* s = (const char*)g_wpack + tid * 16;
        cp16(d, s); cp16(d + 8192, s + 8192);
        cp16(d + 16384, s + 16384); cp16(d + 24576, s + 24576);
        asm volatile("cp.async.commit_group;");
    }

    // ================= input projection =================
    {
        float* s_x  = (float*)(smem + OFF_HN);   // [128][36]
        float* s_pw = (float*)(smem + OFF_T);    // [32][132]
        for (int i = tid; i < 1024; i += THREADS) {
            int r = i >> 5, c4 = i & 31;
            *(float4*)&s_pw[r * LDH + c4 * 4] = *(const float4*)(pw + r * DIM + c4 * 4);
        }
        for (int i = tid; i < 1024; i += THREADS) {
            int r = i >> 3, c4 = i & 7;
            *(float4*)&s_x[r * 36 + c4 * 4] = *(const float4*)(xg + (row0 + r) * FIN + c4 * 4);
        }
        __syncthreads();
        int pr = tid >> 2, qt = tid & 3;
        int colb = qt * 32;
        float4 acc[8];
#pragma unroll
        for (int c4 = 0; c4 < 8; c4++) {
            int col = colb + c4 * 4;
            float4 a = *(const float4*)(pb + col);
            float4 po = *(const float4*)(pos + col);
            acc[c4].x = a.x + po.x; acc[c4].y = a.y + po.y;
            acc[c4].z = a.z + po.z; acc[c4].w = a.w + po.w;
        }
#pragma unroll 8
        for (int k = 0; k < FIN; k++) {
            float a = s_x[pr * 36 + k];
#pragma unroll
            for (int c4 = 0; c4 < 8; c4++) {
                float4 w = *(const float4*)&s_pw[k * LDH + colb + c4 * 4];
                acc[c4].x += a * w.x; acc[c4].y += a * w.y;
                acc[c4].z += a * w.z; acc[c4].w += a * w.w;
            }
        }
        __syncthreads();
#pragma unroll
        for (int c4 = 0; c4 < 8; c4++)
            *(float4*)&s_h[pr * LDH + colb + c4 * 4] = acc[c4];
        __syncthreads();
    }

    // ============================ 8 expert slots ============================
    for (int slot = 0; slot < NL * KSEL; slot++) {
        int blk = g_sel[slot];
        size_t bo = (size_t)((slot >> 1) * NB + blk);
        const float* LS = ln_s + bo * DIM;
        const float* LB = ln_b + bo * DIM;
        if (tid < HID) s_b1[tid] = __ldg(b1g + bo * HID + tid);
        else if (tid < HID + DIM) s_b2[tid - HID] = __ldg(b2g + bo * DIM + (tid - HID));
        else if (tid < HID + 2 * DIM) s_gf[tid - HID - DIM] = g_gfac[slot][tid - HID - DIM];

        // ---- LayerNorm -> s_hn fp16 (warp wid: rows wid*8..) ----
        {
            float4 ls4 = *(const float4*)(LS + lane * 4);
            float4 lb4 = *(const float4*)(LB + lane * 4);
#pragma unroll
            for (int rr = 0; rr < 8; rr++) {
                int r = wid * 8 + rr;
                float4 v = *(const float4*)&s_h[r * LDH + lane * 4];
                float s = v.x + v.y + v.z + v.w;
                float q = v.x * v.x + v.y * v.y + v.z * v.z + v.w * v.w;
#pragma unroll
                for (int o = 16; o > 0; o >>= 1) {
                    s += __shfl_xor_sync(0xffffffffu, s, o);
                    q += __shfl_xor_sync(0xffffffffu, q, o);
                }
                float mu = s * (1.0f / DIM);
                float rstd = rsqrtf(q * (1.0f / DIM) - mu * mu + 1e-5f);
                uint32_t p0 = pkh2((v.x - mu) * rstd * ls4.x + lb4.x,
                                   (v.y - mu) * rstd * ls4.y + lb4.y);
                uint32_t p1 = pkh2((v.z - mu) * rstd * ls4.z + lb4.z,
                                   (v.w - mu) * rstd * ls4.w + lb4.w);
                *(uint2*)&s_hn[r * SHN_LD + lane * 4] = make_uint2(p0, p1);
            }
        }

        float zacc[8][4];
#pragma unroll
        for (int j = 0; j < 8; j++)
#pragma unroll
            for (int e = 0; e < 4; e++) zacc[j][e] = 0.0f;

        for (int half = 0; half < 2; half++) {
#pragma unroll
            for (int g2 = 0; g2 < 2; g2++) {
                int q = slot * 4 + half * 2 + g2;
                // ---- stage: wait current chunk, sync, prefetch next ----
                asm volatile("cp.async.wait_group 0;" ::: "memory");
                __syncthreads();
                {
                    int nq = q + 1;
                    if (nq < 32) {
                        uint32_t d = wb + (nq & 1) * 32768 + tid * 16;
                        const char* s = (const char*)g_wpack + (size_t)nq * 32768 + tid * 16;
                        cp16(d, s); cp16(d + 8192, s + 8192);
                        cp16(d + 16384, s + 16384); cp16(d + 24576, s + 24576);
                    }
                    asm volatile("cp.async.commit_group;");
                }
                const u64* tab = (const u64*)(smem + OFF_WB + (q & 1) * 32768);
                const __half* A = g2 ? s_t : s_hn;

                float c1[8][4];
                if (!g2) {
#pragma unroll
                    for (int j = 0; j < 8; j++)
#pragma unroll
                        for (int e = 0; e < 4; e++) c1[j][e] = 0.0f;
                }
                float (*acc)[4] = g2 ? zacc : c1;

#pragma unroll
                for (int ks = 0; ks < 8; ks++) {
                    int abase = (mrow + g) * SHN_LD + ks * 16 + 2 * tg;
                    uint32_t a0 = *(const uint32_t*)(A + abase);
                    uint32_t a1 = *(const uint32_t*)(A + abase + 8 * SHN_LD);
                    uint32_t a2 = *(const uint32_t*)(A + abase + 8);
                    uint32_t a3 = *(const uint32_t*)(A + abase + 8 * SHN_LD + 8);
                    const u64* bp = tab + (ks * 16 + wn * 8) * 32 + lane;
                    u64 bf[8];
#pragma unroll
                    for (int j = 0; j < 8; j++) bf[j] = bp[j * 32];
#pragma unroll
                    for (int j = 0; j < 8; j++)
                        mma_fp16(acc[j], a0, a1, a2, a3,
                                 (uint32_t)bf[j], (uint32_t)(bf[j] >> 32));
                }

                if (!g2) {
                    // ---- +b1, GELU -> s_t fp16 (next phase's sync orders reads) ----
#pragma unroll
                    for (int j = 0; j < 8; j++) {
                        int col = wn * 64 + j * 8 + 2 * tg;
                        float b0 = s_b1[half * 128 + col];
                        float b1v = s_b1[half * 128 + col + 1];
                        int r = mrow + g;
                        *(uint32_t*)&s_t[r * SHN_LD + col] =
                            pkh2(gelu_exact(acc[j][0] + b0), gelu_exact(acc[j][1] + b1v));
                        *(uint32_t*)&s_t[(r + 8) * SHN_LD + col] =
                            pkh2(gelu_exact(acc[j][2] + b0), gelu_exact(acc[j][3] + b1v));
                    }
                }
            }
        }

        // ---- residual: h += 0.5*(z + b2)*gfac ----
        __syncthreads();   // all warps done with s_t reads & prior s_h reads
#pragma unroll
        for (int j = 0; j < 8; j++) {
            int col = wn * 64 + j * 8 + 2 * tg;
            float b0 = s_b2[col], b1v = s_b2[col + 1];
            float f0 = s_gf[col], f1 = s_gf[col + 1];
            int r = mrow + g;
            float2 hv = *(float2*)&s_h[r * LDH + col];
            hv.x += 0.5f * (zacc[j][0] + b0) * f0;
            hv.y += 0.5f * (zacc[j][1] + b1v) * f1;
            *(float2*)&s_h[r * LDH + col] = hv;
            float2 hw = *(float2*)&s_h[(r + 8) * LDH + col];
            hw.x += 0.5f * (zacc[j][2] + b0) * f0;
            hw.y += 0.5f * (zacc[j][3] + b1v) * f1;
            *(float2*)&s_h[(r + 8) * LDH + col] = hw;
        }
        __syncthreads();
    }

    // ============================ classifier + emit ============================
    {
        float2 cw[4];
#pragma unroll
        for (int ci = 0; ci < 4; ci++)
            cw[ci] = *(const float2*)(cls_w + (lane * 4 + ci) * 2);
        float cb0 = cls_b[0], cb1 = cls_b[1];
#pragma unroll
        for (int rr = 0; rr < 8; rr++) {
            int r = wid * 8 + rr;
            float4 v = *(const float4*)&s_h[r * LDH + lane * 4];
            float a0 = v.x * cw[0].x + v.y * cw[1].x + v.z * cw[2].x + v.w * cw[3].x;
            float a1 = v.x * cw[0].y + v.y * cw[1].y + v.z * cw[2].y + v.w * cw[3].y;
#pragma unroll
            for (int o = 16; o > 0; o >>= 1) {
                a0 += __shfl_xor_sync(0xffffffffu, a0, o);
                a1 += __shfl_xor_sync(0xffffffffu, a1, o);
            }
            if (lane == 0) {
                size_t row = row0 + r;
                out[row * 2]     = a0 + cb0;
                out[row * 2 + 1] = a1 + cb1;
            }
        }
        for (int i = tid; i < ROWS * 32; i += THREADS) {
            int r = i >> 5, c = (i & 31) * 4;
            *(float4*)&out[(size_t)B_TOTAL * 2 + (row0 + r) * DIM + c] =
                *(const float4*)&s_h[r * LDH + c];
        }
    }
}

// ---------------------------------------------------------------------------
extern "C" void kernel_launch(void* const* d_in, const int* in_sizes, int n_in,
                              void* d_out, int out_size) {
    const float* x      = (const float*)d_in[0];
    const float* proj_w = (const float*)d_in[1];
    const float* proj_b = (const float*)d_in[2];
    const float* pos    = (const float*)d_in[3];
    const float* sel_w  = (const float*)d_in[4];
    const float* sel_b  = (const float*)d_in[5];
    const float* ln_s   = (const float*)d_in[6];
    const float* ln_b   = (const float*)d_in[7];
    const float* w1     = (const float*)d_in[8];
    const float* b1     = (const float*)d_in[9];
    const float* w2     = (const float*)d_in[10];
    const float* b2     = (const float*)d_in[11];
    const float* gate   = (const float*)d_in[12];
    const float* cls_w  = (const float*)d_in[13];
    const float* cls_b  = (const float*)d_in[14];
    const float* tf     = (const float*)d_in[15];
    float* out = (float*)d_out;

    cudaFuncSetAttribute(fused_kernel, cudaFuncAttributeMaxDynamicSharedMemorySize, SMEM_TOT);

    pilot_kernel<<<1, 256>>>(x, proj_w, proj_b, pos, sel_w, sel_b, ln_s, ln_b,
                             w1, b1, w2, b2, gate, tf);
    repack_kernel<<<32, 256>>>(w1, w2);
    fused_kernel<<<B_TOTAL / ROWS, THREADS, SMEM_TOT>>>(
        x, proj_w, proj_b, pos, b1, b2, ln_s, ln_b, cls_w, cls_b, out);
}

// round 7
// speedup vs baseline: 3.3384x; 1.2026x over previous
#include <cuda_runtime.h>
#include <cuda_fp16.h>
#include <math.h>
#include <stdint.h>

#define B_TOTAL 131072
#define DIM     128
#define HID     256
#define NB      8
#define NL      4
#define KSEL    2
#define FIN     32
#define ROWS    128
#define LDH     132          // s_h float stride
#define TLW     72           // fp16 tile stride in 32-bit words (144 halves)
#define THREADS 512

typedef unsigned long long u64;

__device__ int   g_sel[NL * KSEL];
__device__ float g_gfac[NL * KSEL][DIM];
// 32 chunks x 32KB fragment tables: u64[ks(8)][jj(16)][lane(32)] per chunk
__device__ __align__(256) uint4 g_wpack[65536];

__device__ __forceinline__ float sigm(float x) { return 1.0f / (1.0f + expf(-x)); }
__device__ __forceinline__ float gelu_exact(float x) {
    return 0.5f * x * (1.0f + erff(x * 0.70710678118654752440f));
}
__device__ __forceinline__ uint32_t pkh2(float x, float y) {
    return (uint32_t)__half_as_ushort(__float2half_rn(x))
         | ((uint32_t)__half_as_ushort(__float2half_rn(y)) << 16);
}
__device__ __forceinline__ void cp16(uint32_t d, const void* s) {
    asm volatile("cp.async.cg.shared.global [%0], [%1], 16;" :: "r"(d), "l"(s));
}
__device__ __forceinline__ void mma_fp16(float c[4], uint32_t a0, uint32_t a1,
                                         uint32_t a2, uint32_t a3,
                                         uint32_t b0, uint32_t b1) {
    asm volatile("mma.sync.aligned.m16n8k16.row.col.f32.f16.f16.f32 "
        "{%0,%1,%2,%3},{%4,%5,%6,%7},{%8,%9},{%0,%1,%2,%3};"
        : "+f"(c[0]), "+f"(c[1]), "+f"(c[2]), "+f"(c[3])
        : "r"(a0), "r"(a1), "r"(a2), "r"(a3), "r"(b0), "r"(b1));
}
// permuted pair slot within a 16-k block: pairs [0,4,1,5,2,6,3,7]
__device__ __forceinline__ int pair_word(int r, int p) {
    int ks = p >> 3, q = p & 7;
    return r * TLW + ks * 8 + (q & 3) * 2 + (q >> 2);
}

// ---------------------------------------------------------------------------
// Pilot: sample-0 trajectory -> routing + gate factors. 1024 threads, split-K.
// ---------------------------------------------------------------------------
__global__ void __launch_bounds__(1024, 1)
pilot_kernel(const float* __restrict__ x, const float* __restrict__ pw,
             const float* __restrict__ pb, const float* __restrict__ pos,
             const float* __restrict__ sel_w, const float* __restrict__ sel_b,
             const float* __restrict__ ln_s, const float* __restrict__ ln_b,
             const float* __restrict__ w1, const float* __restrict__ b1,
             const float* __restrict__ w2, const float* __restrict__ b2,
             const float* __restrict__ gate, const float* __restrict__ tf) {
    __shared__ float h0[DIM], hn[DIM], tbuf[HID], fbuf[DIM];
    __shared__ float part[8][256];
    __shared__ float redA[64], redB[64];
    __shared__ float sc[NB];
    __shared__ int   seli[KSEL];
    __shared__ float s_mu, s_rstd;
    int tid = threadIdx.x, lane = tid & 31, wid = tid >> 5;

    if (tid < DIM) {
        float acc = pb[tid] + pos[tid];
#pragma unroll
        for (int k = 0; k < FIN; k++) acc += x[k] * pw[k * DIM + tid];
        h0[tid] = acc;
    }
    __syncthreads();

    for (int l = 0; l < NL; l++) {
        // selector: thread (b = tid>>7, d = tid&127)
        {
            int b = tid >> 7, d = tid & 127;
            float pv = h0[d] * sel_w[(l * DIM + d) * NB + b];
#pragma unroll
            for (int o = 16; o > 0; o >>= 1) pv += __shfl_xor_sync(0xffffffffu, pv, o);
            if (lane == 0) part[0][wid] = pv;
        }
        __syncthreads();
        if (tid < NB) {
            float s = part[0][tid * 4] + part[0][tid * 4 + 1]
                    + part[0][tid * 4 + 2] + part[0][tid * 4 + 3];
            sc[tid] = sigm(s + sel_b[l * NB + tid]) * 0.6f + 0.2f;
        }
        __syncthreads();
        if (tid == 0) {
            int i0 = 0; float v0 = -1e30f;
            for (int j = 0; j < NB; j++) if (sc[j] > v0) { v0 = sc[j]; i0 = j; }
            int i1 = -1; float v1 = -1e30f;
            for (int j = 0; j < NB; j++) { if (j == i0) continue; if (sc[j] > v1) { v1 = sc[j]; i1 = j; } }
            seli[0] = i0; seli[1] = i1;
            g_sel[l * KSEL + 0] = i0; g_sel[l * KSEL + 1] = i1;
        }
        __syncthreads();

        for (int k = 0; k < KSEL; k++) {
            int i = seli[k];
            size_t bo = (size_t)(l * NB + i);
            if (tid < DIM) {
                float fv = 1.0f + sigm(gate[bo * DIM + tid]) * tf[tid];
                fbuf[tid] = fv;
                g_gfac[l * KSEL + k][tid] = fv;
            }
            if (tid < 64) {
                float a = h0[tid], b = h0[tid + 64];
                redA[tid] = a + b; redB[tid] = a * a + b * b;
            }
            __syncthreads();
            if (tid == 0) {
                float s = 0.f, q = 0.f;
                for (int j = 0; j < 64; j++) { s += redA[j]; q += redB[j]; }
                float mu = s * (1.0f / DIM);
                s_mu = mu;
                s_rstd = rsqrtf(q * (1.0f / DIM) - mu * mu + 1e-5f);
            }
            __syncthreads();
            if (tid < DIM)
                hn[tid] = (h0[tid] - s_mu) * s_rstd * ln_s[bo * DIM + tid] + ln_b[bo * DIM + tid];
            __syncthreads();
            // GEMV1 split-K: col = tid&255, seg = tid>>8 (4 x 32 k)
            {
                int col = tid & 255, seg = tid >> 8, k0 = seg * 32;
                const float* W1 = w1 + bo * DIM * HID;
                float acc = 0.f;
#pragma unroll
                for (int kk = 0; kk < 32; kk++)
                    acc += hn[k0 + kk] * __ldg(&W1[(size_t)(k0 + kk) * HID + col]);
                part[seg][col] = acc;
            }
            __syncthreads();
            if (tid < HID)
                tbuf[tid] = gelu_exact(part[0][tid] + part[1][tid] + part[2][tid] + part[3][tid]
                                       + b1[bo * HID + tid]);
            __syncthreads();
            // GEMV2 split-K: col = tid&127, seg = tid>>7 (8 x 32 k)
            {
                int col = tid & 127, seg = tid >> 7, k0 = seg * 32;
                const float* W2 = w2 + bo * HID * DIM;
                float acc = 0.f;
#pragma unroll
                for (int kk = 0; kk < 32; kk++)
                    acc += tbuf[k0 + kk] * __ldg(&W2[(size_t)(k0 + kk) * DIM + col]);
                part[seg][col] = acc;
            }
            __syncthreads();
            if (tid < DIM) {
                float z = part[0][tid] + part[1][tid] + part[2][tid] + part[3][tid]
                        + part[4][tid] + part[5][tid] + part[6][tid] + part[7][tid]
                        + b2[bo * DIM + tid];
                h0[tid] += 0.5f * z * fbuf[tid];
            }
            __syncthreads();
        }
    }
}

// ---------------------------------------------------------------------------
// Repack: selected experts -> per-lane fp16 fragment tables (unchanged layout)
// ---------------------------------------------------------------------------
__global__ void repack_kernel(const float* __restrict__ w1g, const float* __restrict__ w2g) {
    int q = blockIdx.x;                 // 0..31
    int slot = q >> 2, phase = q & 3;
    int half = phase >> 1;
    bool isG2 = phase & 1;
    int blk = g_sel[slot];
    size_t bo = (size_t)((slot >> 1) * NB + blk);
    const float* W = isG2 ? (w2g + bo * HID * DIM) : (w1g + bo * DIM * HID);
    int ld = isG2 ? DIM : HID;
    u64* dst = (u64*)g_wpack + (size_t)q * 4096;
    for (int e = threadIdx.x; e < 4096; e += 256) {
        int lane = e & 31, jj = (e >> 5) & 15, ks = e >> 9;
        int g = lane >> 2, tg = lane & 3;
        int n, kb;
        if (!isG2) { n = half * 128 + jj * 8 + g; kb = ks * 16; }
        else       { n = jj * 8 + g;              kb = half * 128 + ks * 16; }
        uint32_t lo = pkh2(W[(size_t)(kb + 2 * tg) * ld + n],
                           W[(size_t)(kb + 2 * tg + 1) * ld + n]);
        uint32_t hi = pkh2(W[(size_t)(kb + 2 * tg + 8) * ld + n],
                           W[(size_t)(kb + 2 * tg + 9) * ld + n]);
        dst[e] = (u64)lo | ((u64)hi << 32);
    }
}

// ---------------------------------------------------------------------------
// SMEM byte offsets
// ---------------------------------------------------------------------------
#define OFF_H    0                    // 128*132*4 = 67584
#define OFF_HN   67584                // 128*72*4  = 36864
#define OFF_T    104448               // 128*72*4  = 36864
#define OFF_WB   141312               // 2 x 32768 = 65536
#define OFF_B1   206848               // 1024
#define OFF_B2   207872               // 512
#define OFF_GF   208384               // 512
#define SMEM_TOT 208896

// ---------------------------------------------------------------------------
// Fused: proj -> 8 expert blocks (fp16 mma, paired-K layout) -> classifier
// ---------------------------------------------------------------------------
__global__ void __launch_bounds__(THREADS, 1)
fused_kernel(const float* __restrict__ xg, const float* __restrict__ pw,
             const float* __restrict__ pb, const float* __restrict__ pos,
             const float* __restrict__ b1g, const float* __restrict__ b2g,
             const float* __restrict__ ln_s, const float* __restrict__ ln_b,
             const float* __restrict__ cls_w, const float* __restrict__ cls_b,
             float* __restrict__ out) {
    extern __shared__ char smem[];
    float*    s_h  = (float*)(smem + OFF_H);
    uint32_t* hn32 = (uint32_t*)(smem + OFF_HN);
    uint32_t* t32  = (uint32_t*)(smem + OFF_T);
    float*    s_b1 = (float*)(smem + OFF_B1);
    float*    s_b2 = (float*)(smem + OFF_B2);
    float*    s_gf = (float*)(smem + OFF_GF);

    int tid = threadIdx.x, lane = tid & 31, wid = tid >> 5;
    int wm = wid >> 1, wn = wid & 1;          // 8 x 2 warp grid
    int g = lane >> 2, tg = lane & 3;
    int mrow = wm * 16;
    size_t row0 = (size_t)blockIdx.x * ROWS;
    uint32_t wb = (uint32_t)__cvta_generic_to_shared(smem + OFF_WB);

    // prefetch chunk 0 (overlaps projection)
    {
        uint32_t d = wb + tid * 16;
        const char* s = (const char*)g_wpack + tid * 16;
        cp16(d, s); cp16(d + 8192, s + 8192);
        cp16(d + 16384, s + 16384); cp16(d + 24576, s + 24576);
        asm volatile("cp.async.commit_group;");
    }

    // ================= input projection =================
    {
        float* s_x  = (float*)(smem + OFF_HN);   // [128][36]
        float* s_pw = (float*)(smem + OFF_T);    // [32][132]
        for (int i = tid; i < 1024; i += THREADS) {
            int r = i >> 5, c4 = i & 31;
            *(float4*)&s_pw[r * LDH + c4 * 4] = *(const float4*)(pw + r * DIM + c4 * 4);
        }
        for (int i = tid; i < 1024; i += THREADS) {
            int r = i >> 3, c4 = i & 7;
            *(float4*)&s_x[r * 36 + c4 * 4] = *(const float4*)(xg + (row0 + r) * FIN + c4 * 4);
        }
        __syncthreads();
        int pr = tid >> 2, qt = tid & 3;
        int colb = qt * 32;
        float4 acc[8];
#pragma unroll
        for (int c4 = 0; c4 < 8; c4++) {
            int col = colb + c4 * 4;
            float4 a = *(const float4*)(pb + col);
            float4 po = *(const float4*)(pos + col);
            acc[c4].x = a.x + po.x; acc[c4].y = a.y + po.y;
            acc[c4].z = a.z + po.z; acc[c4].w = a.w + po.w;
        }
#pragma unroll 8
        for (int k = 0; k < FIN; k++) {
            float a = s_x[pr * 36 + k];
#pragma unroll
            for (int c4 = 0; c4 < 8; c4++) {
                float4 w = *(const float4*)&s_pw[k * LDH + colb + c4 * 4];
                acc[c4].x += a * w.x; acc[c4].y += a * w.y;
                acc[c4].z += a * w.z; acc[c4].w += a * w.w;
            }
        }
        __syncthreads();
#pragma unroll
        for (int c4 = 0; c4 < 8; c4++)
            *(float4*)&s_h[pr * LDH + colb + c4 * 4] = acc[c4];
        __syncthreads();
    }

    // ============================ 8 expert slots ============================
    for (int slot = 0; slot < NL * KSEL; slot++) {
        int blk = g_sel[slot];
        size_t bo = (size_t)((slot >> 1) * NB + blk);
        const float* LS = ln_s + bo * DIM;
        const float* LB = ln_b + bo * DIM;
        if (tid < HID) s_b1[tid] = __ldg(b1g + bo * HID + tid);
        else if (tid < HID + DIM) s_b2[tid - HID] = __ldg(b2g + bo * DIM + (tid - HID));
        else if (tid < HID + 2 * DIM) s_gf[tid - HID - DIM] = g_gfac[slot][tid - HID - DIM];

        // ---- LayerNorm -> hn32 (paired-K permuted fp16) ----
        {
            float4 ls4 = *(const float4*)(LS + lane * 4);
            float4 lb4 = *(const float4*)(LB + lane * 4);
            int p0i = lane * 2, p1i = lane * 2 + 1;
#pragma unroll
            for (int rr = 0; rr < 8; rr++) {
                int r = wid * 8 + rr;
                float4 v = *(const float4*)&s_h[r * LDH + lane * 4];
                float s = v.x + v.y + v.z + v.w;
                float q = v.x * v.x + v.y * v.y + v.z * v.z + v.w * v.w;
#pragma unroll
                for (int o = 16; o > 0; o >>= 1) {
                    s += __shfl_xor_sync(0xffffffffu, s, o);
                    q += __shfl_xor_sync(0xffffffffu, q, o);
                }
                float mu = s * (1.0f / DIM);
                float rstd = rsqrtf(q * (1.0f / DIM) - mu * mu + 1e-5f);
                uint32_t pk0 = pkh2((v.x - mu) * rstd * ls4.x + lb4.x,
                                    (v.y - mu) * rstd * ls4.y + lb4.y);
                uint32_t pk1 = pkh2((v.z - mu) * rstd * ls4.z + lb4.z,
                                    (v.w - mu) * rstd * ls4.w + lb4.w);
                hn32[pair_word(r, p0i)] = pk0;
                hn32[pair_word(r, p1i)] = pk1;
            }
        }

        float zacc[8][4];
#pragma unroll
        for (int j = 0; j < 8; j++)
#pragma unroll
            for (int e = 0; e < 4; e++) zacc[j][e] = 0.0f;

        for (int half = 0; half < 2; half++) {
#pragma unroll
            for (int g2 = 0; g2 < 2; g2++) {
                int q = slot * 4 + half * 2 + g2;
                asm volatile("cp.async.wait_group 0;" ::: "memory");
                __syncthreads();
                {
                    int nq = q + 1;
                    if (nq < 32) {
                        uint32_t d = wb + (nq & 1) * 32768 + tid * 16;
                        const char* s = (const char*)g_wpack + (size_t)nq * 32768 + tid * 16;
                        cp16(d, s); cp16(d + 8192, s + 8192);
                        cp16(d + 16384, s + 16384); cp16(d + 24576, s + 24576);
                    }
                    asm volatile("cp.async.commit_group;");
                }
                const u64* tab = (const u64*)(smem + OFF_WB + (q & 1) * 32768);
                const uint32_t* A32 = g2 ? t32 : hn32;

                float c1[8][4];
                if (!g2) {
#pragma unroll
                    for (int j = 0; j < 8; j++)
#pragma unroll
                        for (int e = 0; e < 4; e++) c1[j][e] = 0.0f;
                }
                float (*acc)[4] = g2 ? zacc : c1;

#pragma unroll
                for (int ks = 0; ks < 8; ks++) {
                    int wbase = (mrow + g) * TLW + ks * 8 + 2 * tg;
                    uint2 lo = *(const uint2*)(A32 + wbase);               // a0, a2
                    uint2 hi = *(const uint2*)(A32 + wbase + 8 * TLW);     // a1, a3
                    const u64* bp = tab + (ks * 16 + wn * 8) * 32 + lane;
                    u64 bf[8];
#pragma unroll
                    for (int j = 0; j < 8; j++) bf[j] = bp[j * 32];
#pragma unroll
                    for (int j = 0; j < 8; j++)
                        mma_fp16(acc[j], lo.x, hi.x, lo.y, hi.y,
                                 (uint32_t)bf[j], (uint32_t)(bf[j] >> 32));
                }

                if (!g2) {
                    // ---- +b1, GELU -> t32 (next phase's sync orders reads) ----
#pragma unroll
                    for (int j = 0; j < 8; j++) {
                        int p = wn * 32 + j * 4 + tg;
                        int col = wn * 64 + j * 8 + 2 * tg;
                        float b0 = s_b1[half * 128 + col];
                        float b1v = s_b1[half * 128 + col + 1];
                        int r = mrow + g;
                        t32[pair_word(r, p)] =
                            pkh2(gelu_exact(acc[j][0] + b0), gelu_exact(acc[j][1] + b1v));
                        t32[pair_word(r + 8, p)] =
                            pkh2(gelu_exact(acc[j][2] + b0), gelu_exact(acc[j][3] + b1v));
                    }
                }
            }
        }

        // ---- residual: h += 0.5*(z + b2)*gfac ----
        __syncthreads();
#pragma unroll
        for (int j = 0; j < 8; j++) {
            int col = wn * 64 + j * 8 + 2 * tg;
            float b0 = s_b2[col], b1v = s_b2[col + 1];
            float f0 = s_gf[col], f1 = s_gf[col + 1];
            int r = mrow + g;
            float2 hv = *(float2*)&s_h[r * LDH + col];
            hv.x += 0.5f * (zacc[j][0] + b0) * f0;
            hv.y += 0.5f * (zacc[j][1] + b1v) * f1;
            *(float2*)&s_h[r * LDH + col] = hv;
            float2 hw = *(float2*)&s_h[(r + 8) * LDH + col];
            hw.x += 0.5f * (zacc[j][2] + b0) * f0;
            hw.y += 0.5f * (zacc[j][3] + b1v) * f1;
            *(float2*)&s_h[(r + 8) * LDH + col] = hw;
        }
        __syncthreads();
    }

    // ============================ classifier + emit ============================
    {
        float2 cw[4];
#pragma unroll
        for (int ci = 0; ci < 4; ci++)
            cw[ci] = *(const float2*)(cls_w + (lane * 4 + ci) * 2);
        float cb0 = cls_b[0], cb1 = cls_b[1];
#pragma unroll
        for (int rr = 0; rr < 8; rr++) {
            int r = wid * 8 + rr;
            float4 v = *(const float4*)&s_h[r * LDH + lane * 4];
            float a0 = v.x * cw[0].x + v.y * cw[1].x + v.z * cw[2].x + v.w * cw[3].x;
            float a1 = v.x * cw[0].y + v.y * cw[1].y + v.z * cw[2].y + v.w * cw[3].y;
#pragma unroll
            for (int o = 16; o > 0; o >>= 1) {
                a0 += __shfl_xor_sync(0xffffffffu, a0, o);
                a1 += __shfl_xor_sync(0xffffffffu, a1, o);
            }
            if (lane == 0) {
                size_t row = row0 + r;
                out[row * 2]     = a0 + cb0;
                out[row * 2 + 1] = a1 + cb1;
            }
        }
        for (int i = tid; i < ROWS * 32; i += THREADS) {
            int r = i >> 5, c = (i & 31) * 4;
            *(float4*)&out[(size_t)B_TOTAL * 2 + (row0 + r) * DIM + c] =
                *(const float4*)&s_h[r * LDH + c];
        }
    }
}

// ---------------------------------------------------------------------------
extern "C" void kernel_launch(void* const* d_in, const int* in_sizes, int n_in,
                              void* d_out, int out_size) {
    const float* x      = (const float*)d_in[0];
    const float* proj_w = (const float*)d_in[1];
    const float* proj_b = (const float*)d_in[2];
    const float* pos    = (const float*)d_in[3];
    const float* sel_w  = (const float*)d_in[4];
    const float* sel_b  = (const float*)d_in[5];
    const float* ln_s   = (const float*)d_in[6];
    const float* ln_b   = (const float*)d_in[7];
    const float* w1     = (const float*)d_in[8];
    const float* b1     = (const float*)d_in[9];
    const float* w2     = (const float*)d_in[10];
    const float* b2     = (const float*)d_in[11];
    const float* gate   = (const float*)d_in[12];
    const float* cls_w  = (const float*)d_in[13];
    const float* cls_b  = (const float*)d_in[14];
    const float* tf     = (const float*)d_in[15];
    float* out = (float*)d_out;

    cudaFuncSetAttribute(fused_kernel, cudaFuncAttributeMaxDynamicSharedMemorySize, SMEM_TOT);

    pilot_kernel<<<1, 1024>>>(x, proj_w, proj_b, pos, sel_w, sel_b, ln_s, ln_b,
                              w1, b1, w2, b2, gate, tf);
    repack_kernel<<<32, 256>>>(w1, w2);
    fused_kernel<<<B_TOTAL / ROWS, THREADS, SMEM_TOT>>>(
        x, proj_w, proj_b, pos, b1, b2, ln_s, ln_b, cls_w, cls_b, out);
}

// round 8
// speedup vs baseline: 3.5092x; 1.0511x over previous
#include <cuda_runtime.h>
#include <cuda_fp16.h>
#include <math.h>
#include <stdint.h>

#define B_TOTAL 131072
#define DIM     128
#define HID     256
#define NB      8
#define NL      4
#define KSEL    2
#define FIN     32
#define ROWS    128
#define LDH     132          // s_h float stride
#define TLW     68           // fp16 tile stride in 32-bit words (136 halves)
#define THREADS 512

typedef unsigned long long u64;

__device__ int   g_sel[NL * KSEL];
__device__ float g_gfac[NL * KSEL][DIM];
// 32 chunks x 32KB: [ks(8)][jp(8)][tile4][8n][8k] fp16 tiles for ldmatrix
__device__ __align__(256) uint4 g_wpack[65536];

__device__ __forceinline__ float sigm(float x) { return 1.0f / (1.0f + expf(-x)); }
__device__ __forceinline__ float gelu_exact(float x) {
    return 0.5f * x * (1.0f + erff(x * 0.70710678118654752440f));
}
__device__ __forceinline__ uint32_t pkh2(float x, float y) {
    return (uint32_t)__half_as_ushort(__float2half_rn(x))
         | ((uint32_t)__half_as_ushort(__float2half_rn(y)) << 16);
}
__device__ __forceinline__ void cp16(uint32_t d, const void* s) {
    asm volatile("cp.async.cg.shared.global [%0], [%1], 16;" :: "r"(d), "l"(s));
}
__device__ __forceinline__ void mma_fp16(float c[4], uint32_t a0, uint32_t a1,
                                         uint32_t a2, uint32_t a3,
                                         uint32_t b0, uint32_t b1) {
    asm volatile("mma.sync.aligned.m16n8k16.row.col.f32.f16.f16.f32 "
        "{%0,%1,%2,%3},{%4,%5,%6,%7},{%8,%9},{%0,%1,%2,%3};"
        : "+f"(c[0]), "+f"(c[1]), "+f"(c[2]), "+f"(c[3])
        : "r"(a0), "r"(a1), "r"(a2), "r"(a3), "r"(b0), "r"(b1));
}
__device__ __forceinline__ void ldsm4(uint32_t r[4], uint32_t addr) {
    asm volatile("ldmatrix.sync.aligned.m8n8.x4.shared.b16 {%0,%1,%2,%3}, [%4];"
        : "=r"(r[0]), "=r"(r[1]), "=r"(r[2]), "=r"(r[3]) : "r"(addr));
}

// ---------------------------------------------------------------------------
// Pilot: sample-0 trajectory -> routing + gate factors (split-K, 1024 thr)
// ---------------------------------------------------------------------------
__global__ void __launch_bounds__(1024, 1)
pilot_kernel(const float* __restrict__ x, const float* __restrict__ pw,
             const float* __restrict__ pb, const float* __restrict__ pos,
             const float* __restrict__ sel_w, const float* __restrict__ sel_b,
             const float* __restrict__ ln_s, const float* __restrict__ ln_b,
             const float* __restrict__ w1, const float* __restrict__ b1,
             const float* __restrict__ w2, const float* __restrict__ b2,
             const float* __restrict__ gate, const float* __restrict__ tf) {
    __shared__ float h0[DIM], hn[DIM], tbuf[HID], fbuf[DIM];
    __shared__ float part[8][256];
    __shared__ float redA[64], redB[64];
    __shared__ float sc[NB];
    __shared__ int   seli[KSEL];
    __shared__ float s_mu, s_rstd;
    int tid = threadIdx.x, lane = tid & 31, wid = tid >> 5;

    if (tid < DIM) {
        float acc = pb[tid] + pos[tid];
#pragma unroll
        for (int k = 0; k < FIN; k++) acc += x[k] * pw[k * DIM + tid];
        h0[tid] = acc;
    }
    __syncthreads();

    for (int l = 0; l < NL; l++) {
        {
            int b = tid >> 7, d = tid & 127;
            float pv = h0[d] * sel_w[(l * DIM + d) * NB + b];
#pragma unroll
            for (int o = 16; o > 0; o >>= 1) pv += __shfl_xor_sync(0xffffffffu, pv, o);
            if (lane == 0) part[0][wid] = pv;
        }
        __syncthreads();
        if (tid < NB) {
            float s = part[0][tid * 4] + part[0][tid * 4 + 1]
                    + part[0][tid * 4 + 2] + part[0][tid * 4 + 3];
            sc[tid] = sigm(s + sel_b[l * NB + tid]) * 0.6f + 0.2f;
        }
        __syncthreads();
        if (tid == 0) {
            int i0 = 0; float v0 = -1e30f;
            for (int j = 0; j < NB; j++) if (sc[j] > v0) { v0 = sc[j]; i0 = j; }
            int i1 = -1; float v1 = -1e30f;
            for (int j = 0; j < NB; j++) { if (j == i0) continue; if (sc[j] > v1) { v1 = sc[j]; i1 = j; } }
            seli[0] = i0; seli[1] = i1;
            g_sel[l * KSEL + 0] = i0; g_sel[l * KSEL + 1] = i1;
        }
        __syncthreads();

        for (int k = 0; k < KSEL; k++) {
            int i = seli[k];
            size_t bo = (size_t)(l * NB + i);
            if (tid < DIM) {
                float fv = 1.0f + sigm(gate[bo * DIM + tid]) * tf[tid];
                fbuf[tid] = fv;
                g_gfac[l * KSEL + k][tid] = fv;
            }
            if (tid < 64) {
                float a = h0[tid], b = h0[tid + 64];
                redA[tid] = a + b; redB[tid] = a * a + b * b;
            }
            __syncthreads();
            if (tid == 0) {
                float s = 0.f, q = 0.f;
                for (int j = 0; j < 64; j++) { s += redA[j]; q += redB[j]; }
                float mu = s * (1.0f / DIM);
                s_mu = mu;
                s_rstd = rsqrtf(q * (1.0f / DIM) - mu * mu + 1e-5f);
            }
            __syncthreads();
            if (tid < DIM)
                hn[tid] = (h0[tid] - s_mu) * s_rstd * ln_s[bo * DIM + tid] + ln_b[bo * DIM + tid];
            __syncthreads();
            {
                int col = tid & 255, seg = tid >> 8, k0 = seg * 32;
                const float* W1 = w1 + bo * DIM * HID;
                float acc = 0.f;
#pragma unroll
                for (int kk = 0; kk < 32; kk++)
                    acc += hn[k0 + kk] * __ldg(&W1[(size_t)(k0 + kk) * HID + col]);
                part[seg][col] = acc;
            }
            __syncthreads();
            if (tid < HID)
                tbuf[tid] = gelu_exact(part[0][tid] + part[1][tid] + part[2][tid] + part[3][tid]
                                       + b1[bo * HID + tid]);
            __syncthreads();
            {
                int col = tid & 127, seg = tid >> 7, k0 = seg * 32;
                const float* W2 = w2 + bo * HID * DIM;
                float acc = 0.f;
#pragma unroll
                for (int kk = 0; kk < 32; kk++)
                    acc += tbuf[k0 + kk] * __ldg(&W2[(size_t)(k0 + kk) * DIM + col]);
                part[seg][col] = acc;
            }
            __syncthreads();
            if (tid < DIM) {
                float z = part[0][tid] + part[1][tid] + part[2][tid] + part[3][tid]
                        + part[4][tid] + part[5][tid] + part[6][tid] + part[7][tid]
                        + b2[bo * DIM + tid];
                h0[tid] += 0.5f * z * fbuf[tid];
            }
            __syncthreads();
        }
    }
}

// ---------------------------------------------------------------------------
// Repack: W1/W2 -> ldmatrix tile stream.
// chunk q = slot*4 + phase; phase = half*2 + g2.
// word e2 in [0,8192): k2=e2&3, nl=(e2>>2)&7, t=(e2>>5)&3, jp=(e2>>7)&7, ks=e2>>10
//   j = jp*2 + (t>>1), khalf = t&1, kl = k2*2
//   G1: k = ks*16 + khalf*8 + kl,           n = half*128 + j*8 + nl   (W1, ld=HID)
//   G2: k = half*128 + ks*16 + khalf*8 + kl, n = j*8 + nl             (W2, ld=DIM)
//   word = {W[k][n], W[k+1][n]} fp16x2
// ---------------------------------------------------------------------------
__global__ void repack_kernel(const float* __restrict__ w1g, const float* __restrict__ w2g) {
    int q = blockIdx.x;                 // 0..31
    int slot = q >> 2, phase = q & 3;
    int half = phase >> 1;
    bool isG2 = phase & 1;
    int blk = g_sel[slot];
    size_t bo = (size_t)((slot >> 1) * NB + blk);
    const float* W = isG2 ? (w2g + bo * HID * DIM) : (w1g + bo * DIM * HID);
    int ld = isG2 ? DIM : HID;
    uint32_t* dst = (uint32_t*)g_wpack + (size_t)q * 8192;
    for (int e2 = threadIdx.x; e2 < 8192; e2 += 256) {
        int k2 = e2 & 3, nl = (e2 >> 2) & 7, t = (e2 >> 5) & 3;
        int jp = (e2 >> 7) & 7, ks = e2 >> 10;
        int j = jp * 2 + (t >> 1), kh = t & 1, kl = k2 * 2;
        int k, n;
        if (!isG2) { k = ks * 16 + kh * 8 + kl; n = half * 128 + j * 8 + nl; }
        else       { k = half * 128 + ks * 16 + kh * 8 + kl; n = j * 8 + nl; }
        dst[e2] = pkh2(W[(size_t)k * ld + n], W[(size_t)(k + 1) * ld + n]);
    }
}

// ---------------------------------------------------------------------------
// SMEM byte offsets
// ---------------------------------------------------------------------------
#define OFF_H    0                    // 128*132*4 = 67584
#define OFF_HN   67584                // 128*68*4  = 34816
#define OFF_T    102400               // 128*68*4  = 34816
#define OFF_WB   137216               // 2 x 32768 = 65536
#define OFF_B1   202752               // 1024
#define OFF_B2   203776               // 512
#define OFF_GF   204288               // 512
#define SMEM_TOT 204800

// ---------------------------------------------------------------------------
// Fused: proj -> 8 expert blocks (fp16 mma + ldmatrix) -> classifier
// ---------------------------------------------------------------------------
__global__ void __launch_bounds__(THREADS, 1)
fused_kernel(const float* __restrict__ xg, const float* __restrict__ pw,
             const float* __restrict__ pb, const float* __restrict__ pos,
             const float* __restrict__ b1g, const float* __restrict__ b2g,
             const float* __restrict__ ln_s, const float* __restrict__ ln_b,
             const float* __restrict__ cls_w, const float* __restrict__ cls_b,
             float* __restrict__ out) {
    extern __shared__ char smem[];
    float*    s_h  = (float*)(smem + OFF_H);
    uint32_t* hn32 = (uint32_t*)(smem + OFF_HN);
    uint32_t* t32  = (uint32_t*)(smem + OFF_T);
    float*    s_b1 = (float*)(smem + OFF_B1);
    float*    s_b2 = (float*)(smem + OFF_B2);
    float*    s_gf = (float*)(smem + OFF_GF);

    int tid = threadIdx.x, lane = tid & 31, wid = tid >> 5;
    int wm = wid >> 2, wn = wid & 3;          // 4 x 4 warp grid
    int g = lane >> 2, tg = lane & 3;
    size_t row0 = (size_t)blockIdx.x * ROWS;

    uint32_t base = (uint32_t)__cvta_generic_to_shared(smem);
    uint32_t hnb = base + OFF_HN;
    uint32_t tb  = base + OFF_T;
    uint32_t wb  = base + OFF_WB;

    // ldmatrix per-thread constant offsets
    //   A: row = wm*32 + mt*16 + (lane&15), khalf = lane>>4
    uint32_t aoff = (uint32_t)(((wm * 32 + (lane & 15)) * TLW + (lane >> 4) * 4) * 4);
    //   B: jp = wn*2 + p; addr = ((ks*8 + jp)*128 + lane*4) words
    uint32_t boff = (uint32_t)((wn * 2 * 128 + lane * 4) * 4);

    // prefetch chunk 0 (overlaps projection)
    {
        uint32_t d = wb + tid * 16;
        const char* s = (const char*)g_wpack + tid * 16;
        cp16(d, s); cp16(d + 8192, s + 8192);
        cp16(d + 16384, s + 16384); cp16(d + 24576, s + 24576);
        asm volatile("cp.async.commit_group;");
    }

    // ================= input projection =================
    {
        float* s_x  = (float*)(smem + OFF_HN);   // [128][36]
        float* s_pw = (float*)(smem + OFF_T);    // [32][132]
        for (int i = tid; i < 1024; i += THREADS) {
            int r = i >> 5, c4 = i & 31;
            *(float4*)&s_pw[r * LDH + c4 * 4] = *(const float4*)(pw + r * DIM + c4 * 4);
        }
        for (int i = tid; i < 1024; i += THREADS) {
            int r = i >> 3, c4 = i & 7;
            *(float4*)&s_x[r * 36 + c4 * 4] = *(const float4*)(xg + (row0 + r) * FIN + c4 * 4);
        }
        __syncthreads();
        int pr = tid >> 2, qt = tid & 3;
        int colb = qt * 32;
        float4 acc[8];
#pragma unroll
        for (int c4 = 0; c4 < 8; c4++) {
            int col = colb + c4 * 4;
            float4 a = *(const float4*)(pb + col);
            float4 po = *(const float4*)(pos + col);
            acc[c4].x = a.x + po.x; acc[c4].y = a.y + po.y;
            acc[c4].z = a.z + po.z; acc[c4].w = a.w + po.w;
        }
#pragma unroll 8
        for (int k = 0; k < FIN; k++) {
            float a = s_x[pr * 36 + k];
#pragma unroll
            for (int c4 = 0; c4 < 8; c4++) {
                float4 w = *(const float4*)&s_pw[k * LDH + colb + c4 * 4];
                acc[c4].x += a * w.x; acc[c4].y += a * w.y;
                acc[c4].z += a * w.z; acc[c4].w += a * w.w;
            }
        }
        __syncthreads();
#pragma unroll
        for (int c4 = 0; c4 < 8; c4++)
            *(float4*)&s_h[pr * LDH + colb + c4 * 4] = acc[c4];
        __syncthreads();
    }

    // ============================ 8 expert slots ============================
    for (int slot = 0; slot < NL * KSEL; slot++) {
        int blk = g_sel[slot];
        size_t bo = (size_t)((slot >> 1) * NB + blk);
        const float* LS = ln_s + bo * DIM;
        const float* LB = ln_b + bo * DIM;
        if (tid < HID) s_b1[tid] = __ldg(b1g + bo * HID + tid);
        else if (tid < HID + DIM) s_b2[tid - HID] = __ldg(b2g + bo * DIM + (tid - HID));
        else if (tid < HID + 2 * DIM) s_gf[tid - HID - DIM] = g_gfac[slot][tid - HID - DIM];

        // ---- LayerNorm -> hn32 (row-major fp16, stride TLW words) ----
        {
            float4 ls4 = *(const float4*)(LS + lane * 4);
            float4 lb4 = *(const float4*)(LB + lane * 4);
#pragma unroll
            for (int rr = 0; rr < 8; rr++) {
                int r = wid * 8 + rr;
                float4 v = *(const float4*)&s_h[r * LDH + lane * 4];
                float s = v.x + v.y + v.z + v.w;
                float q = v.x * v.x + v.y * v.y + v.z * v.z + v.w * v.w;
#pragma unroll
                for (int o = 16; o > 0; o >>= 1) {
                    s += __shfl_xor_sync(0xffffffffu, s, o);
                    q += __shfl_xor_sync(0xffffffffu, q, o);
                }
                float mu = s * (1.0f / DIM);
                float rstd = rsqrtf(q * (1.0f / DIM) - mu * mu + 1e-5f);
                uint2 pk;
                pk.x = pkh2((v.x - mu) * rstd * ls4.x + lb4.x,
                            (v.y - mu) * rstd * ls4.y + lb4.y);
                pk.y = pkh2((v.z - mu) * rstd * ls4.z + lb4.z,
                            (v.w - mu) * rstd * ls4.w + lb4.w);
                *(uint2*)&hn32[r * TLW + lane * 2] = pk;
            }
        }

        float zacc[2][4][4];
#pragma unroll
        for (int mt = 0; mt < 2; mt++)
#pragma unroll
            for (int j = 0; j < 4; j++)
#pragma unroll
                for (int e = 0; e < 4; e++) zacc[mt][j][e] = 0.0f;

        for (int half = 0; half < 2; half++) {
#pragma unroll
            for (int g2 = 0; g2 < 2; g2++) {
                int q = slot * 4 + half * 2 + g2;
                asm volatile("cp.async.wait_group 0;" ::: "memory");
                __syncthreads();
                {
                    int nq = q + 1;
                    if (nq < 32) {
                        uint32_t d = wb + (nq & 1) * 32768 + tid * 16;
                        const char* s = (const char*)g_wpack + (size_t)nq * 32768 + tid * 16;
                        cp16(d, s); cp16(d + 8192, s + 8192);
                        cp16(d + 16384, s + 16384); cp16(d + 24576, s + 24576);
                    }
                    asm volatile("cp.async.commit_group;");
                }
                uint32_t wbc = wb + (q & 1) * 32768;
                uint32_t Ab = (g2 ? tb : hnb) + aoff;

                float c1[2][4][4];
                if (!g2) {
#pragma unroll
                    for (int mt = 0; mt < 2; mt++)
#pragma unroll
                        for (int j = 0; j < 4; j++)
#pragma unroll
                            for (int e = 0; e < 4; e++) c1[mt][j][e] = 0.0f;
                }
                float (*acc)[4][4] = g2 ? zacc : c1;

#pragma unroll
                for (int ks = 0; ks < 8; ks++) {
                    uint32_t b0[4], b1f[4];
                    ldsm4(b0,  wbc + boff + ks * 4096);
                    ldsm4(b1f, wbc + boff + ks * 4096 + 512);
                    uint32_t a0[4], a1[4];
                    ldsm4(a0, Ab + ks * 32);
                    ldsm4(a1, Ab + ks * 32 + 16 * TLW * 4);
#pragma unroll
                    for (int j = 0; j < 4; j++) {
                        uint32_t fb0 = (j < 2) ? b0[(j & 1) * 2]     : b1f[(j & 1) * 2];
                        uint32_t fb1 = (j < 2) ? b0[(j & 1) * 2 + 1] : b1f[(j & 1) * 2 + 1];
                        mma_fp16(acc[0][j], a0[0], a0[1], a0[2], a0[3], fb0, fb1);
                        mma_fp16(acc[1][j], a1[0], a1[1], a1[2], a1[3], fb0, fb1);
                    }
                }

                if (!g2) {
                    // ---- +b1, GELU -> t32 (next phase's barrier orders reads) ----
#pragma unroll
                    for (int mt = 0; mt < 2; mt++)
#pragma unroll
                        for (int j = 0; j < 4; j++) {
                            int colp = wn * 32 + j * 8 + 2 * tg;
                            float bb0 = s_b1[half * 128 + colp];
                            float bb1 = s_b1[half * 128 + colp + 1];
                            int r = wm * 32 + mt * 16 + g;
                            int cw = wn * 16 + j * 4 + tg;
                            t32[r * TLW + cw] =
                                pkh2(gelu_exact(c1[mt][j][0] + bb0), gelu_exact(c1[mt][j][1] + bb1));
                            t32[(r + 8) * TLW + cw] =
                                pkh2(gelu_exact(c1[mt][j][2] + bb0), gelu_exact(c1[mt][j][3] + bb1));
                        }
                }
            }
        }

        // ---- residual: h += 0.5*(z + b2)*gfac ----
        __syncthreads();
#pragma unroll
        for (int mt = 0; mt < 2; mt++)
#pragma unroll
            for (int j = 0; j < 4; j++) {
                int col = wn * 32 + j * 8 + 2 * tg;
                float bb0 = s_b2[col], bb1 = s_b2[col + 1];
                float f0 = s_gf[col], f1 = s_gf[col + 1];
                int r = wm * 32 + mt * 16 + g;
                float2 hv = *(float2*)&s_h[r * LDH + col];
                hv.x += 0.5f * (zacc[mt][j][0] + bb0) * f0;
                hv.y += 0.5f * (zacc[mt][j][1] + bb1) * f1;
                *(float2*)&s_h[r * LDH + col] = hv;
                float2 hw = *(float2*)&s_h[(r + 8) * LDH + col];
                hw.x += 0.5f * (zacc[mt][j][2] + bb0) * f0;
                hw.y += 0.5f * (zacc[mt][j][3] + bb1) * f1;
                *(float2*)&s_h[(r + 8) * LDH + col] = hw;
            }
        __syncthreads();
    }

    // ============================ classifier + emit ============================
    {
        float2 cw[4];
#pragma unroll
        for (int ci = 0; ci < 4; ci++)
            cw[ci] = *(const float2*)(cls_w + (lane * 4 + ci) * 2);
        float cb0 = cls_b[0], cb1 = cls_b[1];
#pragma unroll
        for (int rr = 0; rr < 8; rr++) {
            int r = wid * 8 + rr;
            float4 v = *(const float4*)&s_h[r * LDH + lane * 4];
            float a0 = v.x * cw[0].x + v.y * cw[1].x + v.z * cw[2].x + v.w * cw[3].x;
            float a1 = v.x * cw[0].y + v.y * cw[1].y + v.z * cw[2].y + v.w * cw[3].y;
#pragma unroll
            for (int o = 16; o > 0; o >>= 1) {
                a0 += __shfl_xor_sync(0xffffffffu, a0, o);
                a1 += __shfl_xor_sync(0xffffffffu, a1, o);
            }
            if (lane == 0) {
                size_t row = row0 + r;
                out[row * 2]     = a0 + cb0;
                out[row * 2 + 1] = a1 + cb1;
            }
        }
        for (int i = tid; i < ROWS * 32; i += THREADS) {
            int r = i >> 5, c = (i & 31) * 4;
            *(float4*)&out[(size_t)B_TOTAL * 2 + (row0 + r) * DIM + c] =
                *(const float4*)&s_h[r * LDH + c];
        }
    }
}

// ---------------------------------------------------------------------------
extern "C" void kernel_launch(void* const* d_in, const int* in_sizes, int n_in,
                              void* d_out, int out_size) {
    const float* x      = (const float*)d_in[0];
    const float* proj_w = (const float*)d_in[1];
    const float* proj_b = (const float*)d_in[2];
    const float* pos    = (const float*)d_in[3];
    const float* sel_w  = (const float*)d_in[4];
    const float* sel_b  = (const float*)d_in[5];
    const float* ln_s   = (const float*)d_in[6];
    const float* ln_b   = (const float*)d_in[7];
    const float* w1     = (const float*)d_in[8];
    const float* b1     = (const float*)d_in[9];
    const float* w2     = (const float*)d_in[10];
    const float* b2     = (const float*)d_in[11];
    const float* gate   = (const float*)d_in[12];
    const float* cls_w  = (const float*)d_in[13];
    const float* cls_b  = (const float*)d_in[14];
    const float* tf     = (const float*)d_in[15];
    float* out = (float*)d_out;

    cudaFuncSetAttribute(fused_kernel, cudaFuncAttributeMaxDynamicSharedMemorySize, SMEM_TOT);

    pilot_kernel<<<1, 1024>>>(x, proj_w, proj_b, pos, sel_w, sel_b, ln_s, ln_b,
                              w1, b1, w2, b2, gate, tf);
    repack_kernel<<<32, 256>>>(w1, w2);
    fused_kernel<<<B_TOTAL / ROWS, THREADS, SMEM_TOT>>>(
        x, proj_w, proj_b, pos, b1, b2, ln_s, ln_b, cls_w, cls_b, out);
}